// round 1
// baseline (speedup 1.0000x reference)
#include <cuda_runtime.h>
#include <cuda_bf16.h>
#include <cstdint>

#define NT 512
#define FEATS 8192
#define VPT (FEATS / NT)        // 16 floats per thread
#define V4PT (VPT / 4)          // 4 float4 per thread

// order-preserving float -> uint key (ascending)
__device__ __forceinline__ unsigned f2key(float f) {
    unsigned b = __float_as_uint(f);
    return (b & 0x80000000u) ? ~b : (b | 0x80000000u);
}
__device__ __forceinline__ float key2f(unsigned k) {
    unsigned b = (k & 0x80000000u) ? (k & 0x7FFFFFFFu) : ~k;
    return __uint_as_float(b);
}

__global__ void __launch_bounds__(NT) rsoftmax_kernel(
    const float* __restrict__ in,
    const float* __restrict__ ratep,
    float* __restrict__ out)
{
    __shared__ float    swe[FEATS];     // 32KB staged numerator
    __shared__ unsigned hist[256];
    __shared__ float    warpred[NT / 32];
    __shared__ unsigned s_prefix;
    __shared__ int      s_k;
    __shared__ float    s_bmax;
    __shared__ float    s_bsum;

    const int tid  = threadIdx.x;
    const int lane = tid & 31;
    const size_t rowoff = (size_t)blockIdx.x * FEATS;
    const float4* __restrict__ inr  = (const float4*)(in + rowoff);
    float4* __restrict__       outr = (float4*)(out + rowoff);

    // ---- load row into registers, track max ----
    float x[VPT];
    float lmax = __int_as_float(0xff800000);
    #pragma unroll
    for (int i = 0; i < V4PT; i++) {
        float4 q = inr[tid + i * NT];
        x[4*i+0] = q.x; x[4*i+1] = q.y; x[4*i+2] = q.z; x[4*i+3] = q.w;
        lmax = fmaxf(lmax, fmaxf(fmaxf(q.x, q.y), fmaxf(q.z, q.w)));
    }
    #pragma unroll
    for (int o = 16; o > 0; o >>= 1)
        lmax = fmaxf(lmax, __shfl_xor_sync(0xffffffffu, lmax, o));
    if (lane == 0) warpred[tid >> 5] = lmax;

    if (tid == 0) {
        float r = ratep[0];
        r = fminf(fmaxf(r, 0.0f), 1.0f);
        int idx = (int)(r * (float)FEATS);   // trunc == floor for r>=0
        if (idx > FEATS - 1) idx = FEATS - 1;  // jnp.take clamps
        s_k = FEATS - 1 - idx;               // ascending rank of descending[idx]
        s_prefix = 0u;
    }
    __syncthreads();
    if (tid < 32) {
        float v = (lane < NT / 32) ? warpred[lane] : __int_as_float(0xff800000);
        #pragma unroll
        for (int o = 8; o > 0; o >>= 1)
            v = fmaxf(v, __shfl_xor_sync(0xffffffffu, v, o));
        if (lane == 0) s_bmax = v;
    }

    // ---- 4-pass MSB radix select for the k-th smallest key ----
    #pragma unroll 1
    for (int pass = 0; pass < 4; pass++) {
        const int shift = 24 - 8 * pass;
        if (tid < 256) hist[tid] = 0u;
        __syncthreads();
        const unsigned prefix = s_prefix;
        const unsigned pmask  = (pass == 0) ? 0u : (0xFFFFFFFFu << (shift + 8));
        #pragma unroll
        for (int i = 0; i < VPT; i++) {
            unsigned kb = f2key(x[i]);
            bool act = ((kb & pmask) == prefix);
            unsigned am = __ballot_sync(0xffffffffu, act);
            if (act) {
                unsigned d  = (kb >> shift) & 0xFFu;
                unsigned mm = __match_any_sync(am, d);   // aggregate same-bin lanes
                if (lane == (__ffs(mm) - 1))
                    atomicAdd(&hist[d], (unsigned)__popc(mm));
            }
        }
        __syncthreads();
        if (tid < 32) {
            unsigned c[8];
            unsigned ls = 0;
            #pragma unroll
            for (int j = 0; j < 8; j++) { c[j] = hist[tid * 8 + j]; ls += c[j]; }
            unsigned incl = ls;
            #pragma unroll
            for (int o = 1; o < 32; o <<= 1) {
                unsigned t = __shfl_up_sync(0xffffffffu, incl, o);
                if (lane >= o) incl += t;
            }
            unsigned excl = incl - ls;
            int k = s_k;
            bool has = ((unsigned)k >= excl) && ((unsigned)k < incl);
            unsigned bal = __ballot_sync(0xffffffffu, has);
            int src = __ffs(bal) - 1;
            if (lane == src) {
                unsigned kk = (unsigned)k - excl;
                unsigned dsel = 0;
                #pragma unroll
                for (int j = 0; j < 8; j++) {
                    if (kk < c[j]) { dsel = (unsigned)j; break; }
                    kk -= c[j];
                }
                s_prefix = prefix | (((unsigned)tid * 8u + dsel) << shift);
                s_k = (int)kk;
            }
        }
        __syncthreads();
    }

    const float thresh = key2f(s_prefix);
    const float mx     = s_bmax;

    // ---- numerator + row sum ----
    float lsum = 0.0f;
    #pragma unroll
    for (int i = 0; i < V4PT; i++) {
        float4 w;
        w.x = fmaxf(x[4*i+0] - thresh, 0.0f) * __expf(x[4*i+0] - mx);
        w.y = fmaxf(x[4*i+1] - thresh, 0.0f) * __expf(x[4*i+1] - mx);
        w.z = fmaxf(x[4*i+2] - thresh, 0.0f) * __expf(x[4*i+2] - mx);
        w.w = fmaxf(x[4*i+3] - thresh, 0.0f) * __expf(x[4*i+3] - mx);
        lsum += (w.x + w.y) + (w.z + w.w);
        ((float4*)swe)[tid + i * NT] = w;
    }
    #pragma unroll
    for (int o = 16; o > 0; o >>= 1)
        lsum += __shfl_xor_sync(0xffffffffu, lsum, o);
    if (lane == 0) warpred[tid >> 5] = lsum;
    __syncthreads();
    if (tid < 32) {
        float v = (lane < NT / 32) ? warpred[lane] : 0.0f;
        #pragma unroll
        for (int o = 8; o > 0; o >>= 1)
            v += __shfl_xor_sync(0xffffffffu, v, o);
        if (lane == 0) s_bsum = v;
    }
    __syncthreads();

    const float inv = 1.0f / s_bsum;
    #pragma unroll
    for (int i = 0; i < V4PT; i++) {
        float4 w = ((float4*)swe)[tid + i * NT];
        w.x *= inv; w.y *= inv; w.z *= inv; w.w *= inv;
        outr[tid + i * NT] = w;
    }
}

extern "C" void kernel_launch(void* const* d_in, const int* in_sizes, int n_in,
                              void* d_out, int out_size)
{
    const float* in   = (const float*)d_in[0];
    const float* rate = (const float*)d_in[1];
    float*       out  = (float*)d_out;
    int rows = in_sizes[0] / FEATS;
    rsoftmax_kernel<<<rows, NT>>>(in, rate, out);
}

// round 2
// speedup vs baseline: 1.5202x; 1.5202x over previous
#include <cuda_runtime.h>
#include <cstdint>

#define NT 512
#define FEATS 8192
#define V4PT 4            // 4 x float4 = 16 floats per thread
#define CAP 2048          // candidate buffer (bin ~102 for normal data; 2048 = huge margin)
#define ONE4 0x01010101u

__global__ void __launch_bounds__(NT, 3) rsoftmax_kernel(
    const float* __restrict__ in,
    const float* __restrict__ ratep,
    float* __restrict__ out)
{
    __shared__ float    cand[CAP];
    __shared__ unsigned warpredu[NT / 32];
    __shared__ float    warpredf[2 * (NT / 32)];
    __shared__ int      s_blo, s_below, s_k, s_cnt;
    __shared__ float    s_mn, s_mx, s_thresh, s_sum;

    const int tid  = threadIdx.x;
    const int lane = tid & 31;
    const int wid  = tid >> 5;
    const size_t rowoff = (size_t)blockIdx.x * FEATS;
    const float4* __restrict__ inr  = (const float4*)(in + rowoff);
    float4* __restrict__       outr = (float4*)(out + rowoff);

    const float NINF = __int_as_float(0xff800000);
    const float PINF = __int_as_float(0x7f800000);

    // ---- load row into registers, track min & max ----
    float x[16];
    float lmax = NINF, lmin = PINF;
    #pragma unroll
    for (int i = 0; i < V4PT; i++) {
        float4 q = inr[tid + i * NT];
        x[4*i+0] = q.x; x[4*i+1] = q.y; x[4*i+2] = q.z; x[4*i+3] = q.w;
        lmax = fmaxf(lmax, fmaxf(fmaxf(q.x, q.y), fmaxf(q.z, q.w)));
        lmin = fminf(lmin, fminf(fminf(q.x, q.y), fminf(q.z, q.w)));
    }
    #pragma unroll
    for (int o = 16; o > 0; o >>= 1) {
        lmax = fmaxf(lmax, __shfl_xor_sync(0xffffffffu, lmax, o));
        lmin = fminf(lmin, __shfl_xor_sync(0xffffffffu, lmin, o));
    }
    if (lane == 0) { warpredf[wid] = lmax; warpredf[16 + wid] = lmin; }

    if (tid == 0) {
        float r = fminf(fmaxf(ratep[0], 0.0f), 1.0f);
        int idx = (int)(r * (float)FEATS);       // trunc, matches int32 cast
        if (idx > FEATS - 1) idx = FEATS - 1;    // jnp.take clamps
        s_k = FEATS - 1 - idx;                   // ascending rank of desc[idx]
        s_blo = 0; s_below = 0; s_cnt = 0;
        s_thresh = 0.0f;
    }
    __syncthreads();
    if (wid == 0) {
        float vmax = (lane < 16) ? warpredf[lane]      : NINF;
        float vmin = (lane < 16) ? warpredf[16 + lane] : PINF;
        #pragma unroll
        for (int o = 8; o > 0; o >>= 1) {
            vmax = fmaxf(vmax, __shfl_xor_sync(0xffffffffu, vmax, o));
            vmin = fminf(vmin, __shfl_xor_sync(0xffffffffu, vmin, o));
        }
        if (lane == 0) { s_mx = vmax; s_mn = vmin; }
    }
    __syncthreads();

    const float mx   = s_mx;
    const float mn   = s_mn;
    const int   kabs = s_k;
    float thresh;

    if (mx > mn) {
        // ---- quantize to 8-bit keys, packed 4 per register ----
        const float scale = 255.0f / (mx - mn);
        const float qbias = -mn * scale;
        unsigned qp[4];
        #pragma unroll
        for (int i = 0; i < 4; i++) {
            unsigned pk = 0;
            #pragma unroll
            for (int j = 0; j < 4; j++) {
                int v = (int)fmaf(x[4*i+j], scale, qbias);
                v = max(0, min(v, 255));
                pk |= ((unsigned)v) << (8 * j);
            }
            qp[i] = pk;
        }

        // ---- 4-way bisection on byte bins: 256 -> 64 -> 16 -> 4 -> 1 ----
        #pragma unroll
        for (int pass = 0; pass < 4; pass++) {
            const int step = 64 >> (2 * pass);
            const int blo  = s_blo;
            const unsigned pv1 = (unsigned)(blo +     step) * ONE4;
            const unsigned pv2 = (unsigned)(blo + 2 * step) * ONE4;
            const unsigned pv3 = (unsigned)(blo + 3 * step) * ONE4;
            unsigned c1 = 0, c2 = 0, c3 = 0;
            #pragma unroll
            for (int i = 0; i < 4; i++) {
                c1 = __dp4a(__vcmpltu4(qp[i], pv1) & ONE4, ONE4, c1);
                c2 = __dp4a(__vcmpltu4(qp[i], pv2) & ONE4, ONE4, c2);
                c3 = __dp4a(__vcmpltu4(qp[i], pv3) & ONE4, ONE4, c3);
            }
            unsigned pk = c1 | (c2 << 10) | (c3 << 20);   // fields <= 512, no carry
            #pragma unroll
            for (int o = 16; o > 0; o >>= 1)
                pk += __shfl_xor_sync(0xffffffffu, pk, o);
            if (lane == 0) warpredu[wid] = pk;
            __syncthreads();
            if (wid == 0) {
                unsigned v = (lane < 16) ? warpredu[lane] : 0u;
                unsigned C1 = v & 1023u, C2 = (v >> 10) & 1023u, C3 = v >> 20;
                #pragma unroll
                for (int o = 8; o > 0; o >>= 1) {
                    C1 += __shfl_xor_sync(0xffffffffu, C1, o);
                    C2 += __shfl_xor_sync(0xffffffffu, C2, o);
                    C3 += __shfl_xor_sync(0xffffffffu, C3, o);
                }
                if (lane == 0) {
                    int bl = blo, nb = s_below;
                    if      (kabs >= (int)C3) { bl += 3 * step; nb = (int)C3; }
                    else if (kabs >= (int)C2) { bl += 2 * step; nb = (int)C2; }
                    else if (kabs >= (int)C1) { bl +=     step; nb = (int)C1; }
                    s_blo = bl; s_below = nb;
                }
            }
            __syncthreads();
        }

        // ---- gather exact candidates of the selected bin ----
        const int b = s_blo;
        int kk = kabs - s_below;
        const unsigned bb = (unsigned)b * ONE4;
        #pragma unroll
        for (int i = 0; i < 4; i++) {
            unsigned m = __vcmpeq4(qp[i], bb);
            if (m) {
                #pragma unroll
                for (int j = 0; j < 4; j++) {
                    if ((m >> (8 * j)) & 1u) {
                        int p = atomicAdd(&s_cnt, 1);
                        if (p < CAP) cand[p] = x[4*i+j];
                    }
                }
            }
        }
        __syncthreads();

        // ---- exact rank-select among candidates (exact float compares) ----
        int m = min(s_cnt, CAP);
        if (kk >= m) kk = m - 1;   // defensive (overflow path only)
        if (kk < 0)  kk = 0;
        for (int j = tid; j < m; j += NT) {
            float v = cand[j];
            int cl = 0, ce = 0;
            for (int t = 0; t < m; t++) {
                float c = cand[t];
                cl += (c <  v);
                ce += (c == v);
            }
            if (cl <= kk && kk < cl + ce) s_thresh = v;
        }
        __syncthreads();
        thresh = s_thresh;
    } else {
        thresh = mx;   // constant row
    }

    // ---- numerator in-place + row sum ----
    float lsum = 0.0f;
    #pragma unroll
    for (int i = 0; i < 16; i++) {
        float w = fmaxf(x[i] - thresh, 0.0f) * __expf(x[i] - mx);
        x[i] = w;
        lsum += w;
    }
    #pragma unroll
    for (int o = 16; o > 0; o >>= 1)
        lsum += __shfl_xor_sync(0xffffffffu, lsum, o);
    if (lane == 0) warpredf[wid] = lsum;
    __syncthreads();
    if (wid == 0) {
        float v = (lane < 16) ? warpredf[lane] : 0.0f;
        #pragma unroll
        for (int o = 8; o > 0; o >>= 1)
            v += __shfl_xor_sync(0xffffffffu, v, o);
        if (lane == 0) s_sum = v;
    }
    __syncthreads();

    const float inv = 1.0f / s_sum;
    #pragma unroll
    for (int i = 0; i < V4PT; i++) {
        float4 w;
        w.x = x[4*i+0] * inv; w.y = x[4*i+1] * inv;
        w.z = x[4*i+2] * inv; w.w = x[4*i+3] * inv;
        outr[tid + i * NT] = w;
    }
}

extern "C" void kernel_launch(void* const* d_in, const int* in_sizes, int n_in,
                              void* d_out, int out_size)
{
    const float* in   = (const float*)d_in[0];
    const float* rate = (const float*)d_in[1];
    float*       out  = (float*)d_out;
    int rows = in_sizes[0] / FEATS;
    rsoftmax_kernel<<<rows, NT>>>(in, rate, out);
}

// round 5
// speedup vs baseline: 1.5823x; 1.0408x over previous
#include <cuda_runtime.h>
#include <cstdint>

#define NT 512
#define FEATS 8192
#define V4PT 4
#define CAP 1024
#define ONE4 0x01010101u
#define L2E 1.4426950408889634f

__device__ __forceinline__ float ex2f(float a) {
    float r; asm("ex2.approx.ftz.f32 %0, %1;" : "=f"(r) : "f"(a)); return r;
}
__device__ __forceinline__ unsigned long long packf2(float lo, float hi) {
    unsigned long long r; asm("mov.b64 %0, {%1, %2};" : "=l"(r) : "f"(lo), "f"(hi)); return r;
}
__device__ __forceinline__ void unpackf2(float& lo, float& hi, unsigned long long p) {
    asm("mov.b64 {%0, %1}, %2;" : "=f"(lo), "=f"(hi) : "l"(p));
}
__device__ __forceinline__ unsigned long long addf2(unsigned long long a, unsigned long long b) {
    unsigned long long r; asm("add.rn.f32x2 %0, %1, %2;" : "=l"(r) : "l"(a), "l"(b)); return r;
}
__device__ __forceinline__ unsigned long long mulf2(unsigned long long a, unsigned long long b) {
    unsigned long long r; asm("mul.rn.f32x2 %0, %1, %2;" : "=l"(r) : "l"(a), "l"(b)); return r;
}

__global__ void __launch_bounds__(NT, 3) rsoftmax_kernel(
    const float* __restrict__ in,
    const float* __restrict__ ratep,
    float* __restrict__ out)
{
    __shared__ float    cand[CAP];
    __shared__ unsigned warpredu[NT / 32];
    __shared__ float    warpredf[2 * (NT / 32)];
    __shared__ int      s_blo, s_below, s_cnt;
    __shared__ float    s_mn, s_mx, s_thresh, s_sum;

    const int tid  = threadIdx.x;
    const int lane = tid & 31;
    const int wid  = tid >> 5;
    const size_t rowoff = (size_t)blockIdx.x * FEATS;
    const float4* __restrict__ inr  = (const float4*)(in + rowoff);
    float4* __restrict__       outr = (float4*)(out + rowoff);

    const float NINF = __int_as_float(0xff800000);
    const float PINF = __int_as_float(0x7f800000);

    // ---- load row into registers, track min & max ----
    float x[16];
    float lmax = NINF, lmin = PINF;
    #pragma unroll
    for (int i = 0; i < V4PT; i++) {
        float4 q = inr[tid + i * NT];
        x[4*i+0] = q.x; x[4*i+1] = q.y; x[4*i+2] = q.z; x[4*i+3] = q.w;
        lmax = fmaxf(lmax, fmaxf(fmaxf(q.x, q.y), fmaxf(q.z, q.w)));
        lmin = fminf(lmin, fminf(fminf(q.x, q.y), fminf(q.z, q.w)));
    }
    #pragma unroll
    for (int o = 16; o > 0; o >>= 1) {
        lmax = fmaxf(lmax, __shfl_xor_sync(0xffffffffu, lmax, o));
        lmin = fminf(lmin, __shfl_xor_sync(0xffffffffu, lmin, o));
    }
    if (lane == 0) { warpredf[wid] = lmax; warpredf[16 + wid] = lmin; }

    // rank k computed redundantly per-thread (broadcast load, no barrier needed)
    float r = fminf(fmaxf(__ldg(ratep), 0.0f), 1.0f);
    int idx = (int)(r * (float)FEATS);       // trunc == int32 cast
    if (idx > FEATS - 1) idx = FEATS - 1;    // jnp.take clamps
    const int kabs = FEATS - 1 - idx;        // ascending rank of desc[idx]

    if (tid == 0) { s_blo = 0; s_below = 0; s_cnt = 0; s_thresh = 0.0f; }
    __syncthreads();
    if (wid == 0) {
        float vmax = (lane < 16) ? warpredf[lane]      : NINF;
        float vmin = (lane < 16) ? warpredf[16 + lane] : PINF;
        #pragma unroll
        for (int o = 8; o > 0; o >>= 1) {
            vmax = fmaxf(vmax, __shfl_xor_sync(0xffffffffu, vmax, o));
            vmin = fminf(vmin, __shfl_xor_sync(0xffffffffu, vmin, o));
        }
        if (lane == 0) { s_mx = vmax; s_mn = vmin; }
    }
    __syncthreads();

    const float mx = s_mx;
    const float mn = s_mn;
    float thresh;

    if (mx > mn) {
        // ---- magic-number quantization to bytes [1,255], PRMT-packed ----
        const float scale = 253.0f / (mx - mn);
        const float qbias = 8388609.0f - mn * scale;   // 2^23 + 1 - mn*scale
        unsigned qp[4];
        #pragma unroll
        for (int i = 0; i < 4; i++) {
            unsigned b0 = __float_as_uint(fmaf(x[4*i+0], scale, qbias));
            unsigned b1 = __float_as_uint(fmaf(x[4*i+1], scale, qbias));
            unsigned b2 = __float_as_uint(fmaf(x[4*i+2], scale, qbias));
            unsigned b3 = __float_as_uint(fmaf(x[4*i+3], scale, qbias));
            unsigned t01 = __byte_perm(b0, b1, 0x0040);
            unsigned t23 = __byte_perm(b2, b3, 0x0040);
            qp[i] = __byte_perm(t01, t23, 0x5410);
        }

        // ---- 4-way bisection on byte bins: 256 -> 64 -> 16 -> 4 -> 1 ----
        #pragma unroll
        for (int pass = 0; pass < 4; pass++) {
            const int step = 64 >> (2 * pass);
            const int blo  = s_blo;
            const unsigned pv1 = (unsigned)(blo +     step) * ONE4;
            const unsigned pv2 = (unsigned)(blo + 2 * step) * ONE4;
            const unsigned pv3 = (unsigned)(blo + 3 * step) * ONE4;
            unsigned c1 = 0, c2 = 0, c3 = 0;
            #pragma unroll
            for (int i = 0; i < 4; i++) {
                c1 = __dp4a(__vsetltu4(qp[i], pv1), ONE4, c1);
                c2 = __dp4a(__vsetltu4(qp[i], pv2), ONE4, c2);
                c3 = __dp4a(__vsetltu4(qp[i], pv3), ONE4, c3);
            }
            unsigned pk = c1 | (c2 << 10) | (c3 << 20);   // per-warp fields <= 512
            #pragma unroll
            for (int o = 16; o > 0; o >>= 1)
                pk += __shfl_xor_sync(0xffffffffu, pk, o);
            if (lane == 0) warpredu[wid] = pk;
            __syncthreads();
            if (wid == 0) {
                unsigned v = (lane < 16) ? warpredu[lane] : 0u;
                unsigned C1 = v & 1023u, C2 = (v >> 10) & 1023u, C3 = v >> 20;
                #pragma unroll
                for (int o = 8; o > 0; o >>= 1) {
                    C1 += __shfl_xor_sync(0xffffffffu, C1, o);
                    C2 += __shfl_xor_sync(0xffffffffu, C2, o);
                    C3 += __shfl_xor_sync(0xffffffffu, C3, o);
                }
                if (lane == 0) {
                    int bl = blo, nb = s_below;
                    if      (kabs >= (int)C3) { bl += 3 * step; nb = (int)C3; }
                    else if (kabs >= (int)C2) { bl += 2 * step; nb = (int)C2; }
                    else if (kabs >= (int)C1) { bl +=     step; nb = (int)C1; }
                    s_blo = bl; s_below = nb;
                }
            }
            __syncthreads();
        }

        // ---- gather exact candidates of the selected bin ----
        const unsigned bb = (unsigned)s_blo * ONE4;
        int kk = kabs - s_below;
        #pragma unroll
        for (int i = 0; i < 4; i++) {
            unsigned m = __vcmpeq4(qp[i], bb);
            if (m) {
                #pragma unroll
                for (int j = 0; j < 4; j++) {
                    if ((m >> (8 * j)) & 1u) {
                        int p = atomicAdd(&s_cnt, 1);
                        if (p < CAP) cand[p] = x[4*i+j];
                    }
                }
            }
        }
        __syncthreads();

        // ---- exact rank-select among candidates (exact float compares) ----
        int m = min(s_cnt, CAP);
        if (kk >= m) kk = m - 1;   // defensive
        if (kk < 0)  kk = 0;
        for (int j = tid; j < m; j += NT) {
            float v = cand[j];
            int cl = 0, ce = 0;
            for (int t = 0; t < m; t++) {
                float c = cand[t];
                cl += (c <  v);
                ce += (c == v);
            }
            if (cl <= kk && kk < cl + ce) s_thresh = v;
        }
        __syncthreads();
        thresh = s_thresh;
    } else {
        thresh = mx;   // constant row
    }

    // ---- numerator + row sum, threshold-anchored exp (const factor cancels) ----
    unsigned long long pw[8];
    unsigned long long acc = packf2(0.0f, 0.0f);
    #pragma unroll
    for (int i = 0; i < 8; i++) {
        float t0 = x[2*i+0] - thresh;
        float t1 = x[2*i+1] - thresh;
        float w0 = fmaxf(t0, 0.0f) * ex2f(t0 * L2E);
        float w1 = fmaxf(t1, 0.0f) * ex2f(t1 * L2E);
        pw[i] = packf2(w0, w1);
        acc = addf2(acc, pw[i]);
    }
    float slo, shi;
    unpackf2(slo, shi, acc);
    float lsum = slo + shi;
    #pragma unroll
    for (int o = 16; o > 0; o >>= 1)
        lsum += __shfl_xor_sync(0xffffffffu, lsum, o);
    if (lane == 0) warpredf[wid] = lsum;
    __syncthreads();
    if (wid == 0) {
        float v = (lane < 16) ? warpredf[lane] : 0.0f;
        #pragma unroll
        for (int o = 8; o > 0; o >>= 1)
            v += __shfl_xor_sync(0xffffffffu, v, o);
        if (lane == 0) s_sum = v;
    }
    __syncthreads();

    const float inv = 1.0f / s_sum;
    const unsigned long long invp = packf2(inv, inv);
    #pragma unroll
    for (int i = 0; i < V4PT; i++) {
        unsigned long long p0 = mulf2(pw[2*i+0], invp);
        unsigned long long p1 = mulf2(pw[2*i+1], invp);
        float4 w;
        unpackf2(w.x, w.y, p0);
        unpackf2(w.z, w.w, p1);
        outr[tid + i * NT] = w;
    }
}

extern "C" void kernel_launch(void* const* d_in, const int* in_sizes, int n_in,
                              void* d_out, int out_size)
{
    const float* in   = (const float*)d_in[0];
    const float* rate = (const float*)d_in[1];
    float*       out  = (float*)d_out;
    int rows = in_sizes[0] / FEATS;
    rsoftmax_kernel<<<rows, NT>>>(in, rate, out);
}

// round 6
// speedup vs baseline: 1.7194x; 1.0867x over previous
#include <cuda_runtime.h>
#include <cstdint>

#define NT 512
#define FEATS 8192
#define V4PT 4
#define CAP 1024
#define ONE4 0x01010101u
#define L2E 1.4426950408889634f

__device__ __forceinline__ float ex2f(float a) {
    float r; asm("ex2.approx.ftz.f32 %0, %1;" : "=f"(r) : "f"(a)); return r;
}

__global__ void __launch_bounds__(NT, 4) rsoftmax_kernel(
    const float* __restrict__ in,
    const float* __restrict__ ratep,
    float* __restrict__ out)
{
    __shared__ float    cand[CAP];
    __shared__ float    wmax[16], wmin[16], wsum[16];
    __shared__ unsigned cntA[4], cntB[4];   // per-pass packed counters (c1|c2<<16, c3)
    __shared__ int      s_cnt;
    __shared__ float    s_thresh;

    const int tid  = threadIdx.x;
    const int lane = tid & 31;
    const int wid  = tid >> 5;
    const size_t rowoff = (size_t)blockIdx.x * FEATS;
    const float4* __restrict__ inr  = (const float4*)(in + rowoff);
    float4* __restrict__       outr = (float4*)(out + rowoff);

    const float NINF = __int_as_float(0xff800000);
    const float PINF = __int_as_float(0x7f800000);

    // ---- load row into registers, track min & max ----
    float x[16];
    {
        float lmax = NINF, lmin = PINF;
        #pragma unroll
        for (int i = 0; i < V4PT; i++) {
            float4 q = inr[tid + i * NT];
            x[4*i+0] = q.x; x[4*i+1] = q.y; x[4*i+2] = q.z; x[4*i+3] = q.w;
            lmax = fmaxf(lmax, fmaxf(fmaxf(q.x, q.y), fmaxf(q.z, q.w)));
            lmin = fminf(lmin, fminf(fminf(q.x, q.y), fminf(q.z, q.w)));
        }
        #pragma unroll
        for (int o = 16; o > 0; o >>= 1) {
            lmax = fmaxf(lmax, __shfl_xor_sync(0xffffffffu, lmax, o));
            lmin = fminf(lmin, __shfl_xor_sync(0xffffffffu, lmin, o));
        }
        if (lane == 0) { wmax[wid] = lmax; wmin[wid] = lmin; }
    }
    if (tid == 0) {
        s_cnt = 0; s_thresh = 0.0f;
        #pragma unroll
        for (int p = 0; p < 4; p++) { cntA[p] = 0u; cntB[p] = 0u; }
    }

    // rank k, redundant per thread (uniform broadcast load)
    float r = fminf(fmaxf(__ldg(ratep), 0.0f), 1.0f);
    int idx = (int)(r * (float)FEATS);       // trunc == int32 cast
    if (idx > FEATS - 1) idx = FEATS - 1;    // jnp.take clamps
    const int kabs = FEATS - 1 - idx;        // ascending rank of desc[idx]

    __syncthreads();                                    // B1

    // redundant all-thread min/max combine (4x LDS.128 each, no warp0 phase)
    float mx, mn;
    {
        const float4* m4 = (const float4*)wmax;
        const float4* n4 = (const float4*)wmin;
        float4 a0 = m4[0], a1 = m4[1], a2 = m4[2], a3 = m4[3];
        float4 b0 = n4[0], b1 = n4[1], b2 = n4[2], b3 = n4[3];
        mx = fmaxf(fmaxf(fmaxf(a0.x,a0.y),fmaxf(a0.z,a0.w)),
                   fmaxf(fmaxf(a1.x,a1.y),fmaxf(a1.z,a1.w)));
        mx = fmaxf(mx, fmaxf(fmaxf(fmaxf(a2.x,a2.y),fmaxf(a2.z,a2.w)),
                             fmaxf(fmaxf(a3.x,a3.y),fmaxf(a3.z,a3.w))));
        mn = fminf(fminf(fminf(b0.x,b0.y),fminf(b0.z,b0.w)),
                   fminf(fminf(b1.x,b1.y),fminf(b1.z,b1.w)));
        mn = fminf(mn, fminf(fminf(fminf(b2.x,b2.y),fminf(b2.z,b2.w)),
                             fminf(fminf(b3.x,b3.y),fminf(b3.z,b3.w))));
    }

    float thresh;
    if (mx > mn) {
        // ---- magic-number quantization to bytes [1,255], PRMT-packed ----
        const float scale = 253.0f / (mx - mn);
        const float qbias = 8388609.0f - mn * scale;   // 2^23 + 1 - mn*scale
        unsigned qp[4];
        #pragma unroll
        for (int i = 0; i < 4; i++) {
            unsigned b0 = __float_as_uint(fmaf(x[4*i+0], scale, qbias));
            unsigned b1 = __float_as_uint(fmaf(x[4*i+1], scale, qbias));
            unsigned b2 = __float_as_uint(fmaf(x[4*i+2], scale, qbias));
            unsigned b3 = __float_as_uint(fmaf(x[4*i+3], scale, qbias));
            unsigned t01 = __byte_perm(b0, b1, 0x0040);
            unsigned t23 = __byte_perm(b2, b3, 0x0040);
            qp[i] = __byte_perm(t01, t23, 0x5410);
        }

        // ---- 4-way bisection: 256 -> 64 -> 16 -> 4 -> 1 (1 barrier/pass, no serial) ----
        int blo = 0, below = 0;
        #pragma unroll
        for (int pass = 0; pass < 4; pass++) {
            const int step = 64 >> (2 * pass);
            const unsigned pv1 = (unsigned)(blo +     step) * ONE4;
            const unsigned pv2 = (unsigned)(blo + 2 * step) * ONE4;
            const unsigned pv3 = (unsigned)(blo + 3 * step) * ONE4;
            unsigned c1 = 0, c2 = 0, c3 = 0;
            #pragma unroll
            for (int i = 0; i < 4; i++) {
                c1 = __dp4a(__vsetltu4(qp[i], pv1), ONE4, c1);
                c2 = __dp4a(__vsetltu4(qp[i], pv2), ONE4, c2);
                c3 = __dp4a(__vsetltu4(qp[i], pv3), ONE4, c3);
            }
            unsigned pk = c1 | (c2 << 10) | (c3 << 20);   // per-warp fields <= 512
            #pragma unroll
            for (int o = 16; o > 0; o >>= 1)
                pk += __shfl_xor_sync(0xffffffffu, pk, o);
            if (lane == 0) {
                unsigned w1 = pk & 1023u, w2 = (pk >> 10) & 1023u, w3 = pk >> 20;
                atomicAdd(&cntA[pass], w1 | (w2 << 16));
                atomicAdd(&cntB[pass], w3);
            }
            __syncthreads();                              // B2..B5
            // redundant decision per thread
            unsigned ca = cntA[pass], C3 = cntB[pass];
            unsigned C1 = ca & 0xFFFFu, C2 = ca >> 16;
            if      (kabs >= (int)C3) { blo += 3 * step; below = (int)C3; }
            else if (kabs >= (int)C2) { blo += 2 * step; below = (int)C2; }
            else if (kabs >= (int)C1) { blo +=     step; below = (int)C1; }
        }

        // ---- gather exact candidates of the selected bin ----
        const unsigned bb = (unsigned)blo * ONE4;
        int kk = kabs - below;
        #pragma unroll
        for (int i = 0; i < 4; i++) {
            unsigned m = __vcmpeq4(qp[i], bb);
            if (m) {
                #pragma unroll
                for (int j = 0; j < 4; j++) {
                    if ((m >> (8 * j)) & 1u) {
                        int p = atomicAdd(&s_cnt, 1);
                        if (p < CAP) cand[p] = x[4*i+j];
                    }
                }
            }
        }
        __syncthreads();                                  // B6

        // ---- exact rank-select among candidates ----
        int m = min(s_cnt, CAP);
        if (kk >= m) kk = m - 1;   // defensive
        if (kk < 0)  kk = 0;
        for (int j = tid; j < m; j += NT) {
            float v = cand[j];
            int cl = 0, ce = 0;
            for (int t = 0; t < m; t++) {
                float c = cand[t];
                cl += (c <  v);
                ce += (c == v);
            }
            if (cl <= kk && kk < cl + ce) s_thresh = v;
        }
        __syncthreads();                                  // B7
        thresh = s_thresh;
    } else {
        thresh = mx;   // constant row (NaN output matches reference 0/0)
    }

    // ---- row sum, threshold-anchored exp (const factor cancels in ratio) ----
    float lsum = 0.0f;
    #pragma unroll
    for (int i = 0; i < 16; i++) {
        float t = x[i] - thresh;
        lsum += fmaxf(t, 0.0f) * ex2f(t * L2E);
    }
    #pragma unroll
    for (int o = 16; o > 0; o >>= 1)
        lsum += __shfl_xor_sync(0xffffffffu, lsum, o);
    if (lane == 0) wsum[wid] = lsum;
    __syncthreads();                                      // B8

    // redundant all-thread sum combine (fixed order -> deterministic)
    float total;
    {
        const float4* s4 = (const float4*)wsum;
        float4 a0 = s4[0], a1 = s4[1], a2 = s4[2], a3 = s4[3];
        total = ((a0.x + a0.y) + (a0.z + a0.w)) + ((a1.x + a1.y) + (a1.z + a1.w))
              + ((a2.x + a2.y) + (a2.z + a2.w)) + ((a3.x + a3.y) + (a3.z + a3.w));
    }
    const float inv = 1.0f / total;

    // ---- recompute numerator, scale, store ----
    #pragma unroll
    for (int i = 0; i < V4PT; i++) {
        float4 o;
        float t0 = x[4*i+0] - thresh;
        float t1 = x[4*i+1] - thresh;
        float t2 = x[4*i+2] - thresh;
        float t3 = x[4*i+3] - thresh;
        o.x = fmaxf(t0, 0.0f) * ex2f(t0 * L2E) * inv;
        o.y = fmaxf(t1, 0.0f) * ex2f(t1 * L2E) * inv;
        o.z = fmaxf(t2, 0.0f) * ex2f(t2 * L2E) * inv;
        o.w = fmaxf(t3, 0.0f) * ex2f(t3 * L2E) * inv;
        outr[tid + i * NT] = o;
    }
}

extern "C" void kernel_launch(void* const* d_in, const int* in_sizes, int n_in,
                              void* d_out, int out_size)
{
    const float* in   = (const float*)d_in[0];
    const float* rate = (const float*)d_in[1];
    float*       out  = (float*)d_out;
    int rows = in_sizes[0] / FEATS;
    rsoftmax_kernel<<<rows, NT>>>(in, rate, out);
}

// round 8
// speedup vs baseline: 1.7492x; 1.0173x over previous
#include <cuda_runtime.h>
#include <cstdint>

#define NT 512
#define FEATS 8192
#define V4PT 4
#define CAP 1024
#define ONE4 0x01010101u
#define L2E 1.4426950408889634f

__device__ __forceinline__ float ex2f(float a) {
    float r; asm("ex2.approx.ftz.f32 %0, %1;" : "=f"(r) : "f"(a)); return r;
}

__global__ void __launch_bounds__(NT, 4) rsoftmax_kernel(
    const float* __restrict__ in,
    const float* __restrict__ ratep,
    float* __restrict__ out)
{
    __shared__ float    sx[FEATS];          // 32KB staged row (x, later w)
    __shared__ float    cand[CAP];          // 4KB candidates (+inf padded)
    __shared__ float    wmax[16], wmin[16], wsum[16];
    __shared__ unsigned cntA[4], cntB[4];   // per-pass packed counters
    __shared__ int      s_cnt;
    __shared__ float    s_thresh;

    const int tid  = threadIdx.x;
    const int lane = tid & 31;
    const int wid  = tid >> 5;
    const size_t rowoff = (size_t)blockIdx.x * FEATS;
    const float4* __restrict__ inr  = (const float4*)(in + rowoff);
    float4* __restrict__       outr = (float4*)(out + rowoff);
    float4* sx4 = (float4*)sx;

    const float NINF = __int_as_float(0xff800000);
    const float PINF = __int_as_float(0x7f800000);

    // ---- pre-init candidate buffer (pads stay +inf) & counters ----
    ((float2*)cand)[tid] = make_float2(PINF, PINF);
    if (tid < 4) { cntA[tid] = 0u; cntB[tid] = 0u; }
    if (tid == 0) { s_cnt = 0; s_thresh = 0.0f; }

    // ---- load row -> smem, track min & max (x transient in regs) ----
    {
        float lmax = NINF, lmin = PINF;
        #pragma unroll
        for (int i = 0; i < V4PT; i++) {
            float4 q = inr[tid + i * NT];
            sx4[tid + i * NT] = q;
            lmax = fmaxf(lmax, fmaxf(fmaxf(q.x, q.y), fmaxf(q.z, q.w)));
            lmin = fminf(lmin, fminf(fminf(q.x, q.y), fminf(q.z, q.w)));
        }
        #pragma unroll
        for (int o = 16; o > 0; o >>= 1) {
            lmax = fmaxf(lmax, __shfl_xor_sync(0xffffffffu, lmax, o));
            lmin = fminf(lmin, __shfl_xor_sync(0xffffffffu, lmin, o));
        }
        if (lane == 0) { wmax[wid] = lmax; wmin[wid] = lmin; }
    }

    // rank k, redundant per thread (uniform broadcast load)
    float r = fminf(fmaxf(__ldg(ratep), 0.0f), 1.0f);
    int idx = (int)(r * (float)FEATS);       // trunc == int32 cast
    if (idx > FEATS - 1) idx = FEATS - 1;    // jnp.take clamps
    const int kabs = FEATS - 1 - idx;        // ascending rank of desc[idx]

    __syncthreads();                                    // B1

    // redundant all-thread min/max combine
    float mx, mn;
    {
        const float4* m4 = (const float4*)wmax;
        const float4* n4 = (const float4*)wmin;
        float4 a0 = m4[0], a1 = m4[1], a2 = m4[2], a3 = m4[3];
        float4 b0 = n4[0], b1 = n4[1], b2 = n4[2], b3 = n4[3];
        mx = fmaxf(fmaxf(fmaxf(a0.x,a0.y),fmaxf(a0.z,a0.w)),
                   fmaxf(fmaxf(a1.x,a1.y),fmaxf(a1.z,a1.w)));
        mx = fmaxf(mx, fmaxf(fmaxf(fmaxf(a2.x,a2.y),fmaxf(a2.z,a2.w)),
                             fmaxf(fmaxf(a3.x,a3.y),fmaxf(a3.z,a3.w))));
        mn = fminf(fminf(fminf(b0.x,b0.y),fminf(b0.z,b0.w)),
                   fminf(fminf(b1.x,b1.y),fminf(b1.z,b1.w)));
        mn = fminf(mn, fminf(fminf(fminf(b2.x,b2.y),fminf(b2.z,b2.w)),
                             fminf(fminf(b3.x,b3.y),fminf(b3.z,b3.w))));
    }

    float thresh;
    if (mx > mn) {
        // ---- magic-number quantization to bytes [1,255] from smem ----
        const float scale = 253.0f / (mx - mn);
        const float qbias = 8388609.0f - mn * scale;   // 2^23 + 1 - mn*scale
        unsigned qp[4];
        #pragma unroll
        for (int i = 0; i < 4; i++) {
            float4 q = sx4[tid + i * NT];
            unsigned b0 = __float_as_uint(fmaf(q.x, scale, qbias));
            unsigned b1 = __float_as_uint(fmaf(q.y, scale, qbias));
            unsigned b2 = __float_as_uint(fmaf(q.z, scale, qbias));
            unsigned b3 = __float_as_uint(fmaf(q.w, scale, qbias));
            unsigned t01 = __byte_perm(b0, b1, 0x0040);
            unsigned t23 = __byte_perm(b2, b3, 0x0040);
            qp[i] = __byte_perm(t01, t23, 0x5410);
        }

        // ---- 4-way bisection: 256 -> 64 -> 16 -> 4 -> 1 ----
        int blo = 0, below = 0;
        #pragma unroll
        for (int pass = 0; pass < 4; pass++) {
            const int step = 64 >> (2 * pass);
            const unsigned pv1 = (unsigned)(blo +     step) * ONE4;
            const unsigned pv2 = (unsigned)(blo + 2 * step) * ONE4;
            const unsigned pv3 = (unsigned)(blo + 3 * step) * ONE4;
            unsigned c1 = 0, c2 = 0, c3 = 0;
            #pragma unroll
            for (int i = 0; i < 4; i++) {
                c1 = __dp4a(__vsetltu4(qp[i], pv1), ONE4, c1);
                c2 = __dp4a(__vsetltu4(qp[i], pv2), ONE4, c2);
                c3 = __dp4a(__vsetltu4(qp[i], pv3), ONE4, c3);
            }
            unsigned pk = c1 | (c2 << 10) | (c3 << 20);   // per-warp fields <= 512
            pk = __reduce_add_sync(0xffffffffu, pk);      // REDUX
            if (lane == 0) {
                unsigned w1 = pk & 1023u, w2 = (pk >> 10) & 1023u, w3 = pk >> 20;
                atomicAdd(&cntA[pass], w1 | (w2 << 16));
                atomicAdd(&cntB[pass], w3);
            }
            __syncthreads();                              // B2..B5
            unsigned ca = cntA[pass], C3 = cntB[pass];
            unsigned C1 = ca & 0xFFFFu, C2 = ca >> 16;
            if      (kabs >= (int)C3) { blo += 3 * step; below = (int)C3; }
            else if (kabs >= (int)C2) { blo += 2 * step; below = (int)C2; }
            else if (kabs >= (int)C1) { blo +=     step; below = (int)C1; }
        }

        // ---- gather exact candidates (scalar LDS only where needed) ----
        const unsigned bb = (unsigned)blo * ONE4;
        int kk = kabs - below;
        #pragma unroll
        for (int i = 0; i < 4; i++) {
            unsigned m = __vcmpeq4(qp[i], bb);
            if (m) {
                #pragma unroll
                for (int j = 0; j < 4; j++) {
                    if ((m >> (8 * j)) & 1u) {
                        int p = atomicAdd(&s_cnt, 1);
                        if (p < CAP) cand[p] = sx[4 * (tid + i * NT) + j];
                    }
                }
            }
        }
        __syncthreads();                                  // B6

        // ---- exact rank-select among candidates (float4 inner loop) ----
        int mm = min(s_cnt, CAP);
        if (kk >= mm) kk = mm - 1;   // defensive
        if (kk < 0)  kk = 0;
        const int t4n = (mm + 3) >> 2;
        const float4* c4 = (const float4*)cand;
        for (int j = tid; j < mm; j += NT) {
            float v = cand[j];
            int cl = 0, ce = 0;
            for (int t = 0; t < t4n; t++) {
                float4 c = c4[t];
                cl += (c.x < v) + (c.y < v) + (c.z < v) + (c.w < v);
                ce += (c.x == v) + (c.y == v) + (c.z == v) + (c.w == v);
            }
            if (cl <= kk && kk < cl + ce) s_thresh = v;
        }
        __syncthreads();                                  // B7
        thresh = s_thresh;
    } else {
        thresh = mx;   // constant row
    }

    // ---- numerator: read x, write w back to smem, accumulate sum ----
    float lsum = 0.0f;
    #pragma unroll
    for (int i = 0; i < V4PT; i++) {
        float4 q = sx4[tid + i * NT];
        float t0 = q.x - thresh, t1 = q.y - thresh;
        float t2 = q.z - thresh, t3 = q.w - thresh;
        float4 w;
        w.x = fmaxf(t0, 0.0f) * ex2f(t0 * L2E);
        w.y = fmaxf(t1, 0.0f) * ex2f(t1 * L2E);
        w.z = fmaxf(t2, 0.0f) * ex2f(t2 * L2E);
        w.w = fmaxf(t3, 0.0f) * ex2f(t3 * L2E);
        sx4[tid + i * NT] = w;
        lsum += (w.x + w.y) + (w.z + w.w);
    }
    #pragma unroll
    for (int o = 16; o > 0; o >>= 1)
        lsum += __shfl_xor_sync(0xffffffffu, lsum, o);
    if (lane == 0) wsum[wid] = lsum;
    __syncthreads();                                      // B8

    float total;
    {
        const float4* s4 = (const float4*)wsum;
        float4 a0 = s4[0], a1 = s4[1], a2 = s4[2], a3 = s4[3];
        total = ((a0.x + a0.y) + (a0.z + a0.w)) + ((a1.x + a1.y) + (a1.z + a1.w))
              + ((a2.x + a2.y) + (a2.z + a2.w)) + ((a3.x + a3.y) + (a3.z + a3.w));
    }
    const float inv = 1.0f / total;

    // ---- scale staged w, store ----
    #pragma unroll
    for (int i = 0; i < V4PT; i++) {
        float4 w = sx4[tid + i * NT];
        w.x *= inv; w.y *= inv; w.z *= inv; w.w *= inv;
        outr[tid + i * NT] = w;
    }
}

extern "C" void kernel_launch(void* const* d_in, const int* in_sizes, int n_in,
                              void* d_out, int out_size)
{
    const float* in   = (const float*)d_in[0];
    const float* rate = (const float*)d_in[1];
    float*       out  = (float*)d_out;
    int rows = in_sizes[0] / FEATS;
    rsoftmax_kernel<<<rows, NT>>>(in, rate, out);
}